// round 2
// baseline (speedup 1.0000x reference)
#include <cuda_runtime.h>

#define THREADS 256
#define G 8
#define NS 4096
#define NF 64
#define NBATCH 32

// pywt db4 dec filters, time-reversed (cross-correlation form)
__device__ __constant__ float cH0[8] = {
     0.23037781330885523f,  0.7148465705525415f,   0.6308807679295904f,
    -0.02798376941698385f, -0.18703481171888114f,  0.030841381835986965f,
     0.032883011666982945f, -0.010597401784997278f };
__device__ __constant__ float cH1[8] = {
    -0.010597401784997278f, -0.032883011666982945f, 0.030841381835986965f,
     0.18703481171888114f,  -0.02798376941698385f,  -0.6308807679295904f,
     0.7148465705525415f,   -0.23037781330885523f };

// One analysis level (levels 2..5): smem in -> smem lo, masked hi -> gmem detail
// plane, and gmem read-modify-write accumulation into the high_freq plane.
// hf rows touched here were written by the SAME thread at level 1 (same n = tid
// + k*THREADS striding), and __syncthreads orders the phases, so the RMW is safe.
template <int TIN>
__device__ __forceinline__ void do_level(const float* __restrict__ in,
                                         float* __restrict__ loOut,
                                         float* __restrict__ det,
                                         float* __restrict__ hf,
                                         unsigned mask)
{
    const int OUTN = TIN / 2;
    for (int n = threadIdx.x; n < OUTN; n += THREADS) {
        float alo[G], ahi[G];
#pragma unroll
        for (int j = 0; j < G; ++j) { alo[j] = 0.f; ahi[j] = 0.f; }
#pragma unroll
        for (int t = 0; t < 8; ++t) {
            int idx = 2 * n + t - 3;
            if (idx >= 0 && idx < TIN) {
                const float* p = in + idx * G;
#pragma unroll
                for (int j = 0; j < G; ++j) {
                    float v = p[j];
                    alo[j] = fmaf(cH0[t], v, alo[j]);
                    ahi[j] = fmaf(cH1[t], v, ahi[j]);
                }
            }
        }
        float dv[G];
#pragma unroll
        for (int j = 0; j < G; ++j) {
            loOut[n * G + j] = alo[j];
            dv[j] = ((mask >> j) & 1u) ? ahi[j] : 0.f;
        }
        float4* pd = (float4*)(det + (size_t)n * NF);
        pd[0] = make_float4(dv[0], dv[1], dv[2], dv[3]);
        pd[1] = make_float4(dv[4], dv[5], dv[6], dv[7]);

        // RMW accumulate into high_freq plane
        float4* ph = (float4*)(hf + (size_t)n * NF);
        float4 h0 = ph[0], h1 = ph[1];
        h0.x += dv[0]; h0.y += dv[1]; h0.z += dv[2]; h0.w += dv[3];
        h1.x += dv[4]; h1.y += dv[5]; h1.z += dv[6]; h1.w += dv[7];
        ph[0] = h0; ph[1] = h1;
    }
    // zero tail of the detail plane
    const float4 z = make_float4(0.f, 0.f, 0.f, 0.f);
    for (int n = OUTN + (int)threadIdx.x; n < NS; n += THREADS) {
        float4* pd = (float4*)(det + (size_t)n * NF);
        pd[0] = z; pd[1] = z;
    }
}

__global__ void __launch_bounds__(THREADS, 2)
dwt_kernel(const float* __restrict__ x, const float* __restrict__ scores,
           float* __restrict__ out)
{
    extern __shared__ float sm[];
    // Peak-live layout (96 KB):
    //   phase L1/L2 : lo1 = sm[0 .. 16384), lo2 = sm[16384 .. 24576)
    //   phase L3+   : lo3 = sm[0 .. 4096), lo4 = sm[4096 .. 6144), lo5 = sm[6144 .. 7168)
    float* lo1 = sm;
    float* lo2 = sm + 2048 * G;
    float* lo3 = sm;
    float* lo4 = sm + 512 * G;
    float* lo5 = sm + 768 * G;

    const int b = blockIdx.x >> 3;
    const int fbase = (blockIdx.x & 7) * G;
    const int tid = threadIdx.x;

    // per-feature decomposition level: 2 + round_half_even(score*3), clamp [2,5]
    int lf[G];
#pragma unroll
    for (int j = 0; j < G; ++j) {
        float sc = __ldg(scores + fbase + j);
        int l = 2 + (int)rintf(sc * 3.0f);
        lf[j] = l < 2 ? 2 : (l > 5 ? 5 : l);
    }
    unsigned msk[5];
#pragma unroll
    for (int i = 0; i < 5; ++i) {
        unsigned m = 0;
#pragma unroll
        for (int j = 0; j < G; ++j) if (i < lf[j]) m |= 1u << j;
        msk[i] = m;     // msk[0], msk[1] always 0xFF (lf >= 2)
    }

    const size_t PLANE = (size_t)NBATCH * NS * NF;         // 8388608
    const size_t rowBase = (size_t)b * NS * NF + fbase;
    float* hf = out + 6 * PLANE + rowBase;                 // high_freq plane

    // ---------------- level 1: conv straight from gmem ----------------
    {
        float* det = out + PLANE + rowBase;                // details[0]
        for (int n = tid; n < 2048; n += THREADS) {
            float alo[G], ahi[G];
#pragma unroll
            for (int j = 0; j < G; ++j) { alo[j] = 0.f; ahi[j] = 0.f; }
#pragma unroll
            for (int t = 0; t < 8; ++t) {
                int idx = 2 * n + t - 3;
                if (idx >= 0 && idx < NS) {
                    const float4* p = (const float4*)(x + rowBase + (size_t)idx * NF);
                    float4 v0 = __ldg(p);
                    float4 v1 = __ldg(p + 1);
                    float vv[G] = { v0.x, v0.y, v0.z, v0.w, v1.x, v1.y, v1.z, v1.w };
#pragma unroll
                    for (int j = 0; j < G; ++j) {
                        alo[j] = fmaf(cH0[t], vv[j], alo[j]);
                        ahi[j] = fmaf(cH1[t], vv[j], ahi[j]);
                    }
                }
            }
#pragma unroll
            for (int j = 0; j < G; ++j)
                lo1[n * G + j] = alo[j];
            float4 a0 = make_float4(ahi[0], ahi[1], ahi[2], ahi[3]);
            float4 a1 = make_float4(ahi[4], ahi[5], ahi[6], ahi[7]);
            float4* pd = (float4*)(det + (size_t)n * NF);
            pd[0] = a0; pd[1] = a1;
            float4* ph = (float4*)(hf + (size_t)n * NF);   // level-1 detail always active
            ph[0] = a0; ph[1] = a1;
        }
        const float4 z = make_float4(0.f, 0.f, 0.f, 0.f);
        for (int n = 2048 + tid; n < NS; n += THREADS) {
            float4* pd = (float4*)(det + (size_t)n * NF);
            pd[0] = z; pd[1] = z;
            float4* ph = (float4*)(hf + (size_t)n * NF);
            ph[0] = z; ph[1] = z;
        }
    }
    __syncthreads();

    do_level<2048>(lo1, lo2, out + 2 * PLANE + rowBase, hf, msk[1]);
    __syncthreads();            // all lo1 reads done before lo3 overwrites sm[0..]
    do_level<1024>(lo2, lo3, out + 3 * PLANE + rowBase, hf, msk[2]);
    __syncthreads();
    do_level< 512>(lo3, lo4, out + 4 * PLANE + rowBase, hf, msk[3]);
    __syncthreads();
    do_level< 256>(lo4, lo5, out + 5 * PLANE + rowBase, hf, msk[4]);
    __syncthreads();

    // ---------------- final pass: approx / low_freq ----------------
    const float* lop[4] = { lo2, lo3, lo4, lo5 };
    const int    lon[4] = { 1024, 512, 256, 128 };
    const float* lpj[G];
    int limj[G];
#pragma unroll
    for (int j = 0; j < G; ++j) {
        lpj[j]  = lop[lf[j] - 2];
        limj[j] = lon[lf[j] - 2];
    }

    float* outA = out + rowBase;                 // approx
    float* outL = out + 7 * PLANE + rowBase;     // low_freq

    for (int s = tid; s < NS; s += THREADS) {
        float av[G];
#pragma unroll
        for (int j = 0; j < G; ++j)
            av[j] = (s < limj[j]) ? lpj[j][s * G + j] : 0.f;
        float4 a0 = make_float4(av[0], av[1], av[2], av[3]);
        float4 a1 = make_float4(av[4], av[5], av[6], av[7]);
        float4* pa = (float4*)(outA + (size_t)s * NF);
        pa[0] = a0; pa[1] = a1;
        float4* pl = (float4*)(outL + (size_t)s * NF);
        pl[0] = a0; pl[1] = a1;
    }
}

extern "C" void kernel_launch(void* const* d_in, const int* in_sizes, int n_in,
                              void* d_out, int out_size)
{
    const float* x      = (const float*)d_in[0];
    const float* scores = (const float*)d_in[1];
    float* out          = (float*)d_out;

    const size_t smem = (size_t)(2048 + 1024) * G * sizeof(float);   // 98304 = 96 KB
    cudaFuncSetAttribute(dwt_kernel, cudaFuncAttributeMaxDynamicSharedMemorySize, (int)smem);

    dwt_kernel<<<NBATCH * (NF / G), THREADS, smem>>>(x, scores, out);
}

// round 3
// speedup vs baseline: 2.2907x; 2.2907x over previous
#include <cuda_runtime.h>

#define G64 64
#define NS 4096
#define NBATCH 32
#define TPB 256

// pywt db4 dec filters, time-reversed (cross-correlation form)
__device__ __constant__ float cH0[8] = {
     0.23037781330885523f,  0.7148465705525415f,   0.6308807679295904f,
    -0.02798376941698385f, -0.18703481171888114f,  0.030841381835986965f,
     0.032883011666982945f, -0.010597401784997278f };
__device__ __constant__ float cH1[8] = {
    -0.010597401784997278f, -0.032883011666982945f, 0.030841381835986965f,
     0.18703481171888114f,  -0.02798376941698385f,  -0.6308807679295904f,
     0.7148465705525415f,   -0.23037781330885523f };

// Lowpass scratch planes, (B, T_k, 64) contiguous. lf >= 2 so lo1 is only an
// intermediate; lo2..lo5 feed the final select.
// sizes (floats): lo1 32*2048*64=4194304, lo2 2097152, lo3 1048576,
//                 lo4 524288, lo5 262144  -> total 8126464 (~31 MB)
__device__ float g_scratch[8126464];
#define OFF_LO1 0
#define OFF_LO2 4194304
#define OFF_LO3 6291456
#define OFF_LO4 7340032
#define OFF_LO5 7864320

__device__ __forceinline__ int level_of(float sc) {
    int l = 2 + (int)rintf(sc * 3.0f);          // round-half-even, matches jnp.round
    return l < 2 ? 2 : (l > 5 ? 5 : l);
}

// One analysis level over full 64-feature rows.
// TIN rows in, TOUT = TIN/2 rows of coefficients; detail plane written for all
// 4096 rows (zero tail). detIdx = 0-based detail index (for the activity mask).
template <int TIN>
__global__ void __launch_bounds__(TPB)
level_kernel(const float* __restrict__ in, float* __restrict__ loOut,
             float* __restrict__ det, const float* __restrict__ scores,
             int detIdx)
{
    const int TOUT = TIN / 2;
    int idx = blockIdx.x * TPB + threadIdx.x;      // (b, n, f4)
    const int f4 = idx & 15;                       // 16 float4 chunks per row
    const int n  = (idx >> 4) & (NS - 1);
    const int b  = idx >> 16;                      // 4096*16 = 65536 per batch

    float4* pd = (float4*)det + (size_t)b * (NS * 16) + n * 16 + f4;
    if (n >= TOUT) {                               // zero tail of detail plane
        *pd = make_float4(0.f, 0.f, 0.f, 0.f);
        return;
    }

    const float4* pin = (const float4*)in + (size_t)b * (TIN * 16) + f4;
    float4 lo = make_float4(0.f, 0.f, 0.f, 0.f);
    float4 hi = make_float4(0.f, 0.f, 0.f, 0.f);
#pragma unroll
    for (int t = 0; t < 8; ++t) {
        int r = 2 * n + t - 3;
        if (r >= 0 && r < TIN) {
            float4 v = __ldg(pin + (size_t)r * 16);
            float c0 = cH0[t], c1 = cH1[t];
            lo.x = fmaf(c0, v.x, lo.x); lo.y = fmaf(c0, v.y, lo.y);
            lo.z = fmaf(c0, v.z, lo.z); lo.w = fmaf(c0, v.w, lo.w);
            hi.x = fmaf(c1, v.x, hi.x); hi.y = fmaf(c1, v.y, hi.y);
            hi.z = fmaf(c1, v.z, hi.z); hi.w = fmaf(c1, v.w, hi.w);
        }
    }
    // per-feature activity mask: detail i populated iff i < lf
    const int f = f4 * 4;
    if (detIdx >= 2) {                              // detIdx 0,1 always active
        if (detIdx >= level_of(__ldg(scores + f + 0))) hi.x = 0.f;
        if (detIdx >= level_of(__ldg(scores + f + 1))) hi.y = 0.f;
        if (detIdx >= level_of(__ldg(scores + f + 2))) hi.z = 0.f;
        if (detIdx >= level_of(__ldg(scores + f + 3))) hi.w = 0.f;
    }
    ((float4*)loOut)[(size_t)b * (TOUT * 16) + n * 16 + f4] = lo;
    *pd = hi;
}

// Final: approx (plane 0), high_freq (plane 6), low_freq (plane 7).
__global__ void __launch_bounds__(TPB)
final_kernel(float* __restrict__ out, const float* __restrict__ scores)
{
    int idx = blockIdx.x * TPB + threadIdx.x;
    const int f4 = idx & 15;
    const int s  = (idx >> 4) & (NS - 1);
    const int b  = idx >> 16;

    const size_t PLANE4 = (size_t)NBATCH * NS * 16;      // float4 units
    const size_t row4   = (size_t)b * (NS * 16) + s * 16 + f4;

    // high_freq = sum of masked detail prefixes (det_k zero for s >= T_k)
    float4 h = make_float4(0.f, 0.f, 0.f, 0.f);
#pragma unroll
    for (int i = 0; i < 5; ++i) {
        if (s < (2048 >> i)) {
            float4 d = __ldg((const float4*)out + (1 + i) * PLANE4 + row4);
            h.x += d.x; h.y += d.y; h.z += d.z; h.w += d.w;
        }
    }
    ((float4*)out)[6 * PLANE4 + row4] = h;

    // approx: per-feature selected lowpass level
    const size_t offs[4] = { OFF_LO2, OFF_LO3, OFF_LO4, OFF_LO5 };
    const int f = f4 * 4;
    float av[4];
#pragma unroll
    for (int j = 0; j < 4; ++j) {
        int k = level_of(__ldg(scores + f + j)) - 2;     // 0..3
        int T = 1024 >> k;
        av[j] = (s < T)
            ? __ldg(g_scratch + offs[k] + (size_t)b * (T * 64) + s * 64 + f + j)
            : 0.f;
    }
    float4 a = make_float4(av[0], av[1], av[2], av[3]);
    ((float4*)out)[row4] = a;               // approx
    ((float4*)out)[7 * PLANE4 + row4] = a;  // low_freq
}

extern "C" void kernel_launch(void* const* d_in, const int* in_sizes, int n_in,
                              void* d_out, int out_size)
{
    const float* x      = (const float*)d_in[0];
    const float* scores = (const float*)d_in[1];
    float* out          = (float*)d_out;

    float* scratch;
    cudaGetSymbolAddress((void**)&scratch, g_scratch);
    float* lo1 = scratch + OFF_LO1;
    float* lo2 = scratch + OFF_LO2;
    float* lo3 = scratch + OFF_LO3;
    float* lo4 = scratch + OFF_LO4;
    float* lo5 = scratch + OFF_LO5;

    const size_t PLANE = (size_t)NBATCH * NS * G64;
    const int grid = (NBATCH * NS * 16) / TPB;          // 8192 blocks

    level_kernel<4096><<<grid, TPB>>>(x,   lo1, out + 1 * PLANE, scores, 0);
    level_kernel<2048><<<grid, TPB>>>(lo1, lo2, out + 2 * PLANE, scores, 1);
    level_kernel<1024><<<grid, TPB>>>(lo2, lo3, out + 3 * PLANE, scores, 2);
    level_kernel< 512><<<grid, TPB>>>(lo3, lo4, out + 4 * PLANE, scores, 3);
    level_kernel< 256><<<grid, TPB>>>(lo4, lo5, out + 5 * PLANE, scores, 4);
    final_kernel<<<grid, TPB>>>(out, scores);
}